// round 14
// baseline (speedup 1.0000x reference)
#include <cuda_runtime.h>
#include <cuda_fp16.h>
#include <cstdint>
#include <math.h>

#define T_DIM 2048
#define B_DIM 32
#define D_DIM 512
#define M_DIM (T_DIM * B_DIM)     // 65536
#define KGL   512

// ---------------------------------------------------------------------------
// Device-global scratch
// ---------------------------------------------------------------------------
__device__ __half g_zgh[(size_t)M_DIM * 2 * D_DIM];   // zg fp16; later y fp16
__device__ __half g_xh [(size_t)M_DIM * D_DIM];       // x fp16
__device__ __half g_hh [(size_t)M_DIM * D_DIM];       // h fp16
__device__ __half g_wih[2 * D_DIM * D_DIM];           // W_in  fp16
__device__ __half g_woh[D_DIM * D_DIM];               // W_out fp16

// ---------------------------------------------------------------------------
// Helpers
// ---------------------------------------------------------------------------
__device__ __forceinline__ uint32_t s2u(const void* p) {
    return (uint32_t)__cvta_generic_to_shared(p);
}
__device__ __forceinline__ uint32_t swz(uint32_t off) {
    return off ^ ((off >> 3) & 0x70);
}
__device__ __forceinline__ void cpa16(uint32_t saddr, const void* g) {
    asm volatile("cp.async.cg.shared.global [%0], [%1], 16;" :: "r"(saddr), "l"(g));
}
#define CP_COMMIT() asm volatile("cp.async.commit_group;" ::: "memory")
#define CP_WAIT1()  asm volatile("cp.async.wait_group 1;" ::: "memory")
#define CP_WAIT0()  asm volatile("cp.async.wait_group 0;" ::: "memory")

__device__ __forceinline__ void ldsm4(uint32_t& r0, uint32_t& r1,
                                      uint32_t& r2, uint32_t& r3, uint32_t a) {
    asm volatile("ldmatrix.sync.aligned.m8n8.x4.shared.b16 {%0,%1,%2,%3}, [%4];"
                 : "=r"(r0), "=r"(r1), "=r"(r2), "=r"(r3) : "r"(a));
}
__device__ __forceinline__ void mma16816(float& c0, float& c1, float& c2, float& c3,
                                         uint32_t a0, uint32_t a1, uint32_t a2, uint32_t a3,
                                         uint32_t b0, uint32_t b1) {
    asm volatile(
        "mma.sync.aligned.m16n8k16.row.col.f32.f16.f16.f32 "
        "{%0,%1,%2,%3}, {%4,%5,%6,%7}, {%8,%9}, {%0,%1,%2,%3};"
        : "+f"(c0), "+f"(c1), "+f"(c2), "+f"(c3)
        : "r"(a0), "r"(a1), "r"(a2), "r"(a3), "r"(b0), "r"(b1));
}
__device__ __forceinline__ void mma16816h(uint32_t& c0, uint32_t& c1,
                                          uint32_t a0, uint32_t a1, uint32_t a2, uint32_t a3,
                                          uint32_t b0, uint32_t b1) {
    asm volatile(
        "mma.sync.aligned.m16n8k16.row.col.f16.f16.f16.f16 "
        "{%0,%1}, {%2,%3,%4,%5}, {%6,%7}, {%0,%1};"
        : "+r"(c0), "+r"(c1)
        : "r"(a0), "r"(a1), "r"(a2), "r"(a3), "r"(b0), "r"(b1));
}

// ---------------------------------------------------------------------------
// Merged fp32 -> fp16 convert for x, W_in, W_out (one launch)
// ---------------------------------------------------------------------------
#define N4_X  ((size_t)M_DIM * D_DIM / 4)
#define N4_WI ((size_t)2 * D_DIM * D_DIM / 4)
#define N4_WO ((size_t)D_DIM * D_DIM / 4)

__global__ void cvt_all_kernel(const float* __restrict__ x,
                               const float* __restrict__ wi,
                               const float* __restrict__ wo,
                               __half* __restrict__ xh,
                               __half* __restrict__ wih,
                               __half* __restrict__ woh)
{
    size_t i = blockIdx.x * (size_t)blockDim.x + threadIdx.x;
    const float* in; __half* out; size_t j;
    if (i < N4_X)                      { in = x;  out = xh;  j = i; }
    else if (i < N4_X + N4_WI)         { in = wi; out = wih; j = i - N4_X; }
    else if (i < N4_X + N4_WI + N4_WO) { in = wo; out = woh; j = i - N4_X - N4_WI; }
    else return;
    float4 v = ((const float4*)in)[j];
    ((__half2*)out)[2 * j]     = __floats2half2_rn(v.x, v.y);
    ((__half2*)out)[2 * j + 1] = __floats2half2_rn(v.z, v.w);
}

// ---------------------------------------------------------------------------
// GEMM common config (R10/R13 proven skeleton)
// ---------------------------------------------------------------------------
#define BK        64
#define STAGES    3
#define TILE_B    (128 * 128)
#define STAGE_B   (2 * TILE_B)
#define SMEM_GEMM (STAGES * STAGE_B)       // 98304

__device__ __forceinline__ void load_stage(
    uint32_t sbase, int s, int chunk, int m0, int n0, int tid,
    const __half* __restrict__ A, const __half* __restrict__ W)
{
    const int k0 = chunk * BK;
    uint32_t stA = sbase + s * STAGE_B;
    uint32_t stW = stA + TILE_B;

    #pragma unroll
    for (int i = 0; i < 4; i++) {
        int g   = tid + i * 256;
        int row = g >> 3;
        int c16 = g & 7;
        uint32_t so = swz(row * 128 + c16 * 16);
        cpa16(stA + so, A + (size_t)(m0 + row) * KGL + k0 + c16 * 8);
        cpa16(stW + so, W + (size_t)(n0 + row) * KGL + k0 + c16 * 8);
    }
    CP_COMMIT();
}

// ---------------------------------------------------------------------------
// GEMM1: fp32-accumulate, fp16 out (zg)
// ---------------------------------------------------------------------------
__global__ __launch_bounds__(256, 2)
void gemm_mma(const __half* __restrict__ A, const __half* __restrict__ W,
              const float* __restrict__ bias, __half* __restrict__ C, int N)
{
    extern __shared__ char smem[];
    const uint32_t sb = s2u(smem);
    const int tid    = threadIdx.x;
    const int lane   = tid & 31;
    const int wid    = tid >> 5;
    const int warp_m = wid & 3;
    const int warp_n = wid >> 2;
    const int m0 = blockIdx.y * 128;
    const int n0 = blockIdx.x * 128;
    const int NCHUNK = KGL / BK;

    uint32_t a_off[2], b_off[4];
    #pragma unroll
    for (int mf = 0; mf < 2; mf++) {
        uint32_t row = warp_m * 32 + mf * 16 + (lane & 15);
        a_off[mf] = swz(row * 128 + (lane >> 4) * 16);
    }
    #pragma unroll
    for (int nf2 = 0; nf2 < 4; nf2++) {
        uint32_t row = warp_n * 64 + nf2 * 16 + (lane & 7) + ((lane >> 4) << 3);
        b_off[nf2] = swz(row * 128 + ((lane >> 3) & 1) * 16);
    }

    float acc[2][8][4];
    #pragma unroll
    for (int i = 0; i < 2; i++)
        #pragma unroll
        for (int j = 0; j < 8; j++)
            #pragma unroll
            for (int q = 0; q < 4; q++) acc[i][j][q] = 0.f;

    load_stage(sb, 0, 0, m0, n0, tid, A, W);
    load_stage(sb, 1, 1, m0, n0, tid, A, W);

    uint32_t af[2][2][4];
    uint32_t bf[2][8][2];

    #pragma unroll 1
    for (int c = 0; c < NCHUNK; c++) {
        const int s = c % STAGES;
        if (c + 1 < NCHUNK) { CP_WAIT1(); } else { CP_WAIT0(); }
        __syncthreads();
        if (c + 2 < NCHUNK)
            load_stage(sb, (c + 2) % STAGES, c + 2, m0, n0, tid, A, W);

        const uint32_t stA = sb + s * STAGE_B;
        const uint32_t stW = stA + TILE_B;

        #pragma unroll
        for (int mf = 0; mf < 2; mf++)
            ldsm4(af[0][mf][0], af[0][mf][1], af[0][mf][2], af[0][mf][3],
                  stA + a_off[mf]);
        #pragma unroll
        for (int nf2 = 0; nf2 < 4; nf2++) {
            uint32_t r0, r1, r2, r3;
            ldsm4(r0, r1, r2, r3, stW + b_off[nf2]);
            bf[0][nf2 * 2][0] = r0; bf[0][nf2 * 2][1] = r1;
            bf[0][nf2 * 2 + 1][0] = r2; bf[0][nf2 * 2 + 1][1] = r3;
        }

        #pragma unroll
        for (int ks = 0; ks < 4; ks++) {
            const int cur = ks & 1;
            const int nxt = cur ^ 1;
            if (ks < 3) {
                const uint32_t kx = (ks + 1) * 32;
                #pragma unroll
                for (int mf = 0; mf < 2; mf++)
                    ldsm4(af[nxt][mf][0], af[nxt][mf][1], af[nxt][mf][2], af[nxt][mf][3],
                          stA + (a_off[mf] ^ kx));
                #pragma unroll
                for (int nf2 = 0; nf2 < 4; nf2++) {
                    uint32_t r0, r1, r2, r3;
                    ldsm4(r0, r1, r2, r3, stW + (b_off[nf2] ^ kx));
                    bf[nxt][nf2 * 2][0] = r0; bf[nxt][nf2 * 2][1] = r1;
                    bf[nxt][nf2 * 2 + 1][0] = r2; bf[nxt][nf2 * 2 + 1][1] = r3;
                }
            }
            #pragma unroll
            for (int mf = 0; mf < 2; mf++)
                #pragma unroll
                for (int nf = 0; nf < 8; nf++)
                    mma16816(acc[mf][nf][0], acc[mf][nf][1], acc[mf][nf][2], acc[mf][nf][3],
                             af[cur][mf][0], af[cur][mf][1], af[cur][mf][2], af[cur][mf][3],
                             bf[cur][nf][0], bf[cur][nf][1]);
        }
    }

    #pragma unroll
    for (int mf = 0; mf < 2; mf++) {
        int r0 = m0 + warp_m * 32 + mf * 16 + (lane >> 2);
        #pragma unroll
        for (int nf = 0; nf < 8; nf++) {
            int n = n0 + warp_n * 64 + nf * 8 + (lane & 3) * 2;
            float bx = bias[n], by = bias[n + 1];
            *(__half2*)(C + (size_t)r0 * N + n) =
                __floats2half2_rn(acc[mf][nf][0] + bx, acc[mf][nf][1] + by);
            *(__half2*)(C + (size_t)(r0 + 8) * N + n) =
                __floats2half2_rn(acc[mf][nf][2] + bx, acc[mf][nf][3] + by);
        }
    }
}

// ---------------------------------------------------------------------------
// GEMM2: fp16-accumulate; epilogue fuses residual: Y = Xh + acc + bias (fp16)
// ---------------------------------------------------------------------------
__global__ __launch_bounds__(256, 2)
void gemm_mma_h16y(const __half* __restrict__ A, const __half* __restrict__ W,
                   const float* __restrict__ bias, const __half* __restrict__ Xh,
                   __half* __restrict__ Y, int N)
{
    extern __shared__ char smem[];
    const uint32_t sb = s2u(smem);
    const int tid    = threadIdx.x;
    const int lane   = tid & 31;
    const int wid    = tid >> 5;
    const int warp_m = wid & 3;
    const int warp_n = wid >> 2;
    const int m0 = blockIdx.y * 128;
    const int n0 = blockIdx.x * 128;
    const int NCHUNK = KGL / BK;

    uint32_t a_off[2], b_off[4];
    #pragma unroll
    for (int mf = 0; mf < 2; mf++) {
        uint32_t row = warp_m * 32 + mf * 16 + (lane & 15);
        a_off[mf] = swz(row * 128 + (lane >> 4) * 16);
    }
    #pragma unroll
    for (int nf2 = 0; nf2 < 4; nf2++) {
        uint32_t row = warp_n * 64 + nf2 * 16 + (lane & 7) + ((lane >> 4) << 3);
        b_off[nf2] = swz(row * 128 + ((lane >> 3) & 1) * 16);
    }

    uint32_t acc[2][8][2];
    #pragma unroll
    for (int i = 0; i < 2; i++)
        #pragma unroll
        for (int j = 0; j < 8; j++) { acc[i][j][0] = 0u; acc[i][j][1] = 0u; }

    load_stage(sb, 0, 0, m0, n0, tid, A, W);
    load_stage(sb, 1, 1, m0, n0, tid, A, W);

    uint32_t af[2][2][4];
    uint32_t bf[2][8][2];

    #pragma unroll 1
    for (int c = 0; c < NCHUNK; c++) {
        const int s = c % STAGES;
        if (c + 1 < NCHUNK) { CP_WAIT1(); } else { CP_WAIT0(); }
        __syncthreads();
        if (c + 2 < NCHUNK)
            load_stage(sb, (c + 2) % STAGES, c + 2, m0, n0, tid, A, W);

        const uint32_t stA = sb + s * STAGE_B;
        const uint32_t stW = stA + TILE_B;

        #pragma unroll
        for (int mf = 0; mf < 2; mf++)
            ldsm4(af[0][mf][0], af[0][mf][1], af[0][mf][2], af[0][mf][3],
                  stA + a_off[mf]);
        #pragma unroll
        for (int nf2 = 0; nf2 < 4; nf2++) {
            uint32_t r0, r1, r2, r3;
            ldsm4(r0, r1, r2, r3, stW + b_off[nf2]);
            bf[0][nf2 * 2][0] = r0; bf[0][nf2 * 2][1] = r1;
            bf[0][nf2 * 2 + 1][0] = r2; bf[0][nf2 * 2 + 1][1] = r3;
        }

        #pragma unroll
        for (int ks = 0; ks < 4; ks++) {
            const int cur = ks & 1;
            const int nxt = cur ^ 1;
            if (ks < 3) {
                const uint32_t kx = (ks + 1) * 32;
                #pragma unroll
                for (int mf = 0; mf < 2; mf++)
                    ldsm4(af[nxt][mf][0], af[nxt][mf][1], af[nxt][mf][2], af[nxt][mf][3],
                          stA + (a_off[mf] ^ kx));
                #pragma unroll
                for (int nf2 = 0; nf2 < 4; nf2++) {
                    uint32_t r0, r1, r2, r3;
                    ldsm4(r0, r1, r2, r3, stW + (b_off[nf2] ^ kx));
                    bf[nxt][nf2 * 2][0] = r0; bf[nxt][nf2 * 2][1] = r1;
                    bf[nxt][nf2 * 2 + 1][0] = r2; bf[nxt][nf2 * 2 + 1][1] = r3;
                }
            }
            #pragma unroll
            for (int mf = 0; mf < 2; mf++)
                #pragma unroll
                for (int nf = 0; nf < 8; nf++)
                    mma16816h(acc[mf][nf][0], acc[mf][nf][1],
                              af[cur][mf][0], af[cur][mf][1], af[cur][mf][2], af[cur][mf][3],
                              bf[cur][nf][0], bf[cur][nf][1]);
        }
    }

    // Fused epilogue: Y = Xh + acc + bias (all fp16)
    #pragma unroll
    for (int mf = 0; mf < 2; mf++) {
        int r0 = m0 + warp_m * 32 + mf * 16 + (lane >> 2);
        #pragma unroll
        for (int nf = 0; nf < 8; nf++) {
            int n = n0 + warp_n * 64 + nf * 8 + (lane & 3) * 2;
            __half2 bias2 = __floats2half2_rn(bias[n], bias[n + 1]);
            __half2 x0 = *(const __half2*)(Xh + (size_t)r0 * N + n);
            __half2 x1 = *(const __half2*)(Xh + (size_t)(r0 + 8) * N + n);
            __half2 v0 = __hadd2(__hadd2(*(__half2*)&acc[mf][nf][0], bias2), x0);
            __half2 v1 = __hadd2(__hadd2(*(__half2*)&acc[mf][nf][1], bias2), x1);
            *(__half2*)(Y + (size_t)r0 * N + n)       = v0;
            *(__half2*)(Y + (size_t)(r0 + 8) * N + n) = v1;
        }
    }
}

// ---------------------------------------------------------------------------
// Chunked gated recurrence over fp16 zg. 16 chunks x 128 steps, 32-step
// warm-up. Writes h as fp16.
// ---------------------------------------------------------------------------
#define SCAN_CHUNKS 16
#define SCAN_L      (T_DIM / SCAN_CHUNKS)   // 128
#define SCAN_W      32

__global__ __launch_bounds__(256)
void scan_kernel(const float* __restrict__ Avec, const float* __restrict__ Bvec)
{
    int idx = blockIdx.x * blockDim.x + threadIdx.x;
    int d = idx & 511;
    int b = (idx >> 9) & 31;
    int chunk = idx >> 14;

    float a_d = Avec[d];
    float b_d = Bvec[d];
    const __half* zg = g_zgh + (size_t)b * (2 * D_DIM) + d;
    __half* hp = g_hh + (size_t)b * D_DIM + d;
    const size_t zs = (size_t)B_DIM * 2 * D_DIM;
    const size_t hs = (size_t)B_DIM * D_DIM;

    const int t0 = chunk * SCAN_L;
    const int tw = (chunk == 0) ? 0 : t0 - SCAN_W;

    float h = 0.f;
    for (int t = tw; t < t0; t += 8) {
        float zz[8], gg[8];
        #pragma unroll
        for (int i = 0; i < 8; i++) {
            zz[i] = __half2float(zg[(size_t)(t + i) * zs]);
            gg[i] = __half2float(zg[(size_t)(t + i) * zs + D_DIM]);
        }
        #pragma unroll
        for (int i = 0; i < 8; i++) {
            float g = 1.f / (1.f + __expf(-gg[i]));
            h = fmaf(g * a_d, h, b_d * zz[i]);
        }
    }
    for (int t = t0; t < t0 + SCAN_L; t += 8) {
        float zz[8], gg[8];
        #pragma unroll
        for (int i = 0; i < 8; i++) {
            zz[i] = __half2float(zg[(size_t)(t + i) * zs]);
            gg[i] = __half2float(zg[(size_t)(t + i) * zs + D_DIM]);
        }
        #pragma unroll
        for (int i = 0; i < 8; i++) {
            float g = 1.f / (1.f + __expf(-gg[i]));
            h = fmaf(g * a_d, h, b_d * zz[i]);
            hp[(size_t)(t + i) * hs] = __float2half_rn(h);
        }
    }
}

// ---------------------------------------------------------------------------
// LayerNorm over fp16 y -> fp32 out
// ---------------------------------------------------------------------------
__global__ __launch_bounds__(128)
void ln_kernel(const __half* __restrict__ y, const float* __restrict__ gamma,
               const float* __restrict__ beta, float* __restrict__ out)
{
    const size_t r = blockIdx.x;
    const __half* yr = y + r * D_DIM;
    float* orow = out + r * D_DIM;
    const int t = threadIdx.x;

    // Each thread: 4 contiguous halves (8B vector load)
    float v[4];
    {
        __half2 p0 = *(const __half2*)(yr + t * 4);
        __half2 p1 = *(const __half2*)(yr + t * 4 + 2);
        float2 f0 = __half22float2(p0);
        float2 f1 = __half22float2(p1);
        v[0] = f0.x; v[1] = f0.y; v[2] = f1.x; v[3] = f1.y;
    }
    float s1 = v[0] + v[1] + v[2] + v[3];
    float s2 = v[0] * v[0] + v[1] * v[1] + v[2] * v[2] + v[3] * v[3];

    #pragma unroll
    for (int off = 16; off; off >>= 1) {
        s1 += __shfl_xor_sync(0xffffffffu, s1, off);
        s2 += __shfl_xor_sync(0xffffffffu, s2, off);
    }
    __shared__ float sh1[4], sh2[4];
    int w = t >> 5;
    if ((t & 31) == 0) { sh1[w] = s1; sh2[w] = s2; }
    __syncthreads();
    s1 = sh1[0] + sh1[1] + sh1[2] + sh1[3];
    s2 = sh2[0] + sh2[1] + sh2[2] + sh2[3];

    float mu  = s1 * (1.f / D_DIM);
    float var = s2 * (1.f / D_DIM) - mu * mu;
    float rs  = rsqrtf(var + 1e-5f);

    float4 o;
    o.x = (v[0] - mu) * rs * gamma[t * 4]     + beta[t * 4];
    o.y = (v[1] - mu) * rs * gamma[t * 4 + 1] + beta[t * 4 + 1];
    o.z = (v[2] - mu) * rs * gamma[t * 4 + 2] + beta[t * 4 + 2];
    o.w = (v[3] - mu) * rs * gamma[t * 4 + 3] + beta[t * 4 + 3];
    *(float4*)(orow + t * 4) = o;
}

// ---------------------------------------------------------------------------
extern "C" void kernel_launch(void* const* d_in, const int* in_sizes, int n_in,
                              void* d_out, int out_size)
{
    const float* x     = (const float*)d_in[0];
    const float* W_in  = (const float*)d_in[1];
    const float* b_in  = (const float*)d_in[2];
    const float* W_out = (const float*)d_in[3];
    const float* b_out = (const float*)d_in[4];
    const float* Avec  = (const float*)d_in[5];
    const float* Bvec  = (const float*)d_in[6];
    const float* gamma = (const float*)d_in[7];
    const float* beta  = (const float*)d_in[8];
    float* out = (float*)d_out;

    __half *zgh, *xh, *hh, *wih, *woh;
    cudaGetSymbolAddress((void**)&zgh, g_zgh);
    cudaGetSymbolAddress((void**)&xh,  g_xh);
    cudaGetSymbolAddress((void**)&hh,  g_hh);
    cudaGetSymbolAddress((void**)&wih, g_wih);
    cudaGetSymbolAddress((void**)&woh, g_woh);

    cudaFuncSetAttribute(gemm_mma, cudaFuncAttributeMaxDynamicSharedMemorySize,
                         SMEM_GEMM);
    cudaFuncSetAttribute(gemm_mma_h16y, cudaFuncAttributeMaxDynamicSharedMemorySize,
                         SMEM_GEMM);

    // Merged converts (x, W_in, W_out -> fp16)
    {
        size_t total = N4_X + N4_WI + N4_WO;
        cvt_all_kernel<<<(unsigned)((total + 255) / 256), 256>>>(
            x, W_in, W_out, xh, wih, woh);
    }

    // GEMM1: zg[M, 2D] = x * W_in^T + b_in  (fp32 acc, fp16 out)
    gemm_mma<<<dim3(2 * D_DIM / 128, M_DIM / 128), 256, SMEM_GEMM>>>(
        xh, wih, b_in, zgh, 2 * D_DIM);

    // Chunked gated scan -> h (fp16); zg fully consumed after this
    scan_kernel<<<(SCAN_CHUNKS * B_DIM * D_DIM) / 256, 256>>>(Avec, Bvec);

    // GEMM2 + residual: y[M, D] = xh + h*W_out^T + b_out  (fp16, into g_zgh)
    gemm_mma_h16y<<<dim3(D_DIM / 128, M_DIM / 128), 256, SMEM_GEMM>>>(
        hh, woh, b_out, xh, zgh, D_DIM);

    // LayerNorm(y) -> out
    ln_kernel<<<M_DIM, 128>>>(zgh, gamma, beta, out);
}

// round 15
// speedup vs baseline: 1.0293x; 1.0293x over previous
#include <cuda_runtime.h>
#include <cuda_fp16.h>
#include <cstdint>
#include <math.h>

#define T_DIM 2048
#define B_DIM 32
#define D_DIM 512
#define M_DIM (T_DIM * B_DIM)     // 65536
#define KGL   512

// ---------------------------------------------------------------------------
// Device-global scratch
// ---------------------------------------------------------------------------
__device__ __half g_zgh[(size_t)M_DIM * 2 * D_DIM];   // [M, 2D] fp16
__device__ __half g_xh [(size_t)M_DIM * D_DIM];       // x fp16
__device__ __half g_ph [(size_t)M_DIM * D_DIM];       // proj fp16
__device__ __half g_hh [(size_t)M_DIM * D_DIM];       // h fp16
__device__ __half g_wih[2 * D_DIM * D_DIM];           // W_in  fp16
__device__ __half g_woh[D_DIM * D_DIM];               // W_out fp16

// ---------------------------------------------------------------------------
// Helpers
// ---------------------------------------------------------------------------
__device__ __forceinline__ uint32_t s2u(const void* p) {
    return (uint32_t)__cvta_generic_to_shared(p);
}
__device__ __forceinline__ uint32_t swz(uint32_t off) {
    return off ^ ((off >> 3) & 0x70);
}
__device__ __forceinline__ void cpa16(uint32_t saddr, const void* g) {
    asm volatile("cp.async.cg.shared.global [%0], [%1], 16;" :: "r"(saddr), "l"(g));
}
#define CP_COMMIT() asm volatile("cp.async.commit_group;" ::: "memory")
#define CP_WAIT1()  asm volatile("cp.async.wait_group 1;" ::: "memory")
#define CP_WAIT0()  asm volatile("cp.async.wait_group 0;" ::: "memory")

__device__ __forceinline__ void ldsm4(uint32_t& r0, uint32_t& r1,
                                      uint32_t& r2, uint32_t& r3, uint32_t a) {
    asm volatile("ldmatrix.sync.aligned.m8n8.x4.shared.b16 {%0,%1,%2,%3}, [%4];"
                 : "=r"(r0), "=r"(r1), "=r"(r2), "=r"(r3) : "r"(a));
}
__device__ __forceinline__ void mma16816(float& c0, float& c1, float& c2, float& c3,
                                         uint32_t a0, uint32_t a1, uint32_t a2, uint32_t a3,
                                         uint32_t b0, uint32_t b1) {
    asm volatile(
        "mma.sync.aligned.m16n8k16.row.col.f32.f16.f16.f32 "
        "{%0,%1,%2,%3}, {%4,%5,%6,%7}, {%8,%9}, {%0,%1,%2,%3};"
        : "+f"(c0), "+f"(c1), "+f"(c2), "+f"(c3)
        : "r"(a0), "r"(a1), "r"(a2), "r"(a3), "r"(b0), "r"(b1));
}
__device__ __forceinline__ void mma16816h(uint32_t& c0, uint32_t& c1,
                                          uint32_t a0, uint32_t a1, uint32_t a2, uint32_t a3,
                                          uint32_t b0, uint32_t b1) {
    asm volatile(
        "mma.sync.aligned.m16n8k16.row.col.f16.f16.f16.f16 "
        "{%0,%1}, {%2,%3,%4,%5}, {%6,%7}, {%0,%1};"
        : "+r"(c0), "+r"(c1)
        : "r"(a0), "r"(a1), "r"(a2), "r"(a3), "r"(b0), "r"(b1));
}

// ---------------------------------------------------------------------------
// Merged fp32 -> fp16 convert for x, W_in, W_out (one launch)
// ---------------------------------------------------------------------------
#define N4_X  ((size_t)M_DIM * D_DIM / 4)
#define N4_WI ((size_t)2 * D_DIM * D_DIM / 4)
#define N4_WO ((size_t)D_DIM * D_DIM / 4)

__global__ void cvt_all_kernel(const float* __restrict__ x,
                               const float* __restrict__ wi,
                               const float* __restrict__ wo,
                               __half* __restrict__ xh,
                               __half* __restrict__ wih,
                               __half* __restrict__ woh)
{
    size_t i = blockIdx.x * (size_t)blockDim.x + threadIdx.x;
    const float* in; __half* out; size_t j;
    if (i < N4_X)                      { in = x;  out = xh;  j = i; }
    else if (i < N4_X + N4_WI)         { in = wi; out = wih; j = i - N4_X; }
    else if (i < N4_X + N4_WI + N4_WO) { in = wo; out = woh; j = i - N4_X - N4_WI; }
    else return;
    float4 v = ((const float4*)in)[j];
    ((__half2*)out)[2 * j]     = __floats2half2_rn(v.x, v.y);
    ((__half2*)out)[2 * j + 1] = __floats2half2_rn(v.z, v.w);
}

// ---------------------------------------------------------------------------
// GEMM common config (R10/R13 proven skeleton)
// ---------------------------------------------------------------------------
#define BK        64
#define STAGES    3
#define TILE_B    (128 * 128)
#define STAGE_B   (2 * TILE_B)
#define SMEM_GEMM (STAGES * STAGE_B)       // 98304

__device__ __forceinline__ void load_stage(
    uint32_t sbase, int s, int chunk, int m0, int n0, int tid,
    const __half* __restrict__ A, const __half* __restrict__ W)
{
    const int k0 = chunk * BK;
    uint32_t stA = sbase + s * STAGE_B;
    uint32_t stW = stA + TILE_B;

    #pragma unroll
    for (int i = 0; i < 4; i++) {
        int g   = tid + i * 256;
        int row = g >> 3;
        int c16 = g & 7;
        uint32_t so = swz(row * 128 + c16 * 16);
        cpa16(stA + so, A + (size_t)(m0 + row) * KGL + k0 + c16 * 8);
        cpa16(stW + so, W + (size_t)(n0 + row) * KGL + k0 + c16 * 8);
    }
    CP_COMMIT();
}

// ---------------------------------------------------------------------------
// GEMM1: fp32-accumulate, fp16 out (zg)
// ---------------------------------------------------------------------------
__global__ __launch_bounds__(256, 2)
void gemm_mma(const __half* __restrict__ A, const __half* __restrict__ W,
              const float* __restrict__ bias, __half* __restrict__ C, int N)
{
    extern __shared__ char smem[];
    const uint32_t sb = s2u(smem);
    const int tid    = threadIdx.x;
    const int lane   = tid & 31;
    const int wid    = tid >> 5;
    const int warp_m = wid & 3;
    const int warp_n = wid >> 2;
    const int m0 = blockIdx.y * 128;
    const int n0 = blockIdx.x * 128;
    const int NCHUNK = KGL / BK;

    uint32_t a_off[2], b_off[4];
    #pragma unroll
    for (int mf = 0; mf < 2; mf++) {
        uint32_t row = warp_m * 32 + mf * 16 + (lane & 15);
        a_off[mf] = swz(row * 128 + (lane >> 4) * 16);
    }
    #pragma unroll
    for (int nf2 = 0; nf2 < 4; nf2++) {
        uint32_t row = warp_n * 64 + nf2 * 16 + (lane & 7) + ((lane >> 4) << 3);
        b_off[nf2] = swz(row * 128 + ((lane >> 3) & 1) * 16);
    }

    float acc[2][8][4];
    #pragma unroll
    for (int i = 0; i < 2; i++)
        #pragma unroll
        for (int j = 0; j < 8; j++)
            #pragma unroll
            for (int q = 0; q < 4; q++) acc[i][j][q] = 0.f;

    load_stage(sb, 0, 0, m0, n0, tid, A, W);
    load_stage(sb, 1, 1, m0, n0, tid, A, W);

    uint32_t af[2][2][4];
    uint32_t bf[2][8][2];

    #pragma unroll 1
    for (int c = 0; c < NCHUNK; c++) {
        const int s = c % STAGES;
        if (c + 1 < NCHUNK) { CP_WAIT1(); } else { CP_WAIT0(); }
        __syncthreads();
        if (c + 2 < NCHUNK)
            load_stage(sb, (c + 2) % STAGES, c + 2, m0, n0, tid, A, W);

        const uint32_t stA = sb + s * STAGE_B;
        const uint32_t stW = stA + TILE_B;

        #pragma unroll
        for (int mf = 0; mf < 2; mf++)
            ldsm4(af[0][mf][0], af[0][mf][1], af[0][mf][2], af[0][mf][3],
                  stA + a_off[mf]);
        #pragma unroll
        for (int nf2 = 0; nf2 < 4; nf2++) {
            uint32_t r0, r1, r2, r3;
            ldsm4(r0, r1, r2, r3, stW + b_off[nf2]);
            bf[0][nf2 * 2][0] = r0; bf[0][nf2 * 2][1] = r1;
            bf[0][nf2 * 2 + 1][0] = r2; bf[0][nf2 * 2 + 1][1] = r3;
        }

        #pragma unroll
        for (int ks = 0; ks < 4; ks++) {
            const int cur = ks & 1;
            const int nxt = cur ^ 1;
            if (ks < 3) {
                const uint32_t kx = (ks + 1) * 32;
                #pragma unroll
                for (int mf = 0; mf < 2; mf++)
                    ldsm4(af[nxt][mf][0], af[nxt][mf][1], af[nxt][mf][2], af[nxt][mf][3],
                          stA + (a_off[mf] ^ kx));
                #pragma unroll
                for (int nf2 = 0; nf2 < 4; nf2++) {
                    uint32_t r0, r1, r2, r3;
                    ldsm4(r0, r1, r2, r3, stW + (b_off[nf2] ^ kx));
                    bf[nxt][nf2 * 2][0] = r0; bf[nxt][nf2 * 2][1] = r1;
                    bf[nxt][nf2 * 2 + 1][0] = r2; bf[nxt][nf2 * 2 + 1][1] = r3;
                }
            }
            #pragma unroll
            for (int mf = 0; mf < 2; mf++)
                #pragma unroll
                for (int nf = 0; nf < 8; nf++)
                    mma16816(acc[mf][nf][0], acc[mf][nf][1], acc[mf][nf][2], acc[mf][nf][3],
                             af[cur][mf][0], af[cur][mf][1], af[cur][mf][2], af[cur][mf][3],
                             bf[cur][nf][0], bf[cur][nf][1]);
        }
    }

    #pragma unroll
    for (int mf = 0; mf < 2; mf++) {
        int r0 = m0 + warp_m * 32 + mf * 16 + (lane >> 2);
        #pragma unroll
        for (int nf = 0; nf < 8; nf++) {
            int n = n0 + warp_n * 64 + nf * 8 + (lane & 3) * 2;
            float bx = bias[n], by = bias[n + 1];
            *(__half2*)(C + (size_t)r0 * N + n) =
                __floats2half2_rn(acc[mf][nf][0] + bx, acc[mf][nf][1] + by);
            *(__half2*)(C + (size_t)(r0 + 8) * N + n) =
                __floats2half2_rn(acc[mf][nf][2] + bx, acc[mf][nf][3] + by);
        }
    }
}

// ---------------------------------------------------------------------------
// GEMM2: fp16-accumulate, plain epilogue -> proj fp16 (R13 proven)
// ---------------------------------------------------------------------------
__global__ __launch_bounds__(256, 2)
void gemm_mma_h16(const __half* __restrict__ A, const __half* __restrict__ W,
                  const float* __restrict__ bias, __half* __restrict__ C, int N)
{
    extern __shared__ char smem[];
    const uint32_t sb = s2u(smem);
    const int tid    = threadIdx.x;
    const int lane   = tid & 31;
    const int wid    = tid >> 5;
    const int warp_m = wid & 3;
    const int warp_n = wid >> 2;
    const int m0 = blockIdx.y * 128;
    const int n0 = blockIdx.x * 128;
    const int NCHUNK = KGL / BK;

    uint32_t a_off[2], b_off[4];
    #pragma unroll
    for (int mf = 0; mf < 2; mf++) {
        uint32_t row = warp_m * 32 + mf * 16 + (lane & 15);
        a_off[mf] = swz(row * 128 + (lane >> 4) * 16);
    }
    #pragma unroll
    for (int nf2 = 0; nf2 < 4; nf2++) {
        uint32_t row = warp_n * 64 + nf2 * 16 + (lane & 7) + ((lane >> 4) << 3);
        b_off[nf2] = swz(row * 128 + ((lane >> 3) & 1) * 16);
    }

    uint32_t acc[2][8][2];
    #pragma unroll
    for (int i = 0; i < 2; i++)
        #pragma unroll
        for (int j = 0; j < 8; j++) { acc[i][j][0] = 0u; acc[i][j][1] = 0u; }

    load_stage(sb, 0, 0, m0, n0, tid, A, W);
    load_stage(sb, 1, 1, m0, n0, tid, A, W);

    uint32_t af[2][2][4];
    uint32_t bf[2][8][2];

    #pragma unroll 1
    for (int c = 0; c < NCHUNK; c++) {
        const int s = c % STAGES;
        if (c + 1 < NCHUNK) { CP_WAIT1(); } else { CP_WAIT0(); }
        __syncthreads();
        if (c + 2 < NCHUNK)
            load_stage(sb, (c + 2) % STAGES, c + 2, m0, n0, tid, A, W);

        const uint32_t stA = sb + s * STAGE_B;
        const uint32_t stW = stA + TILE_B;

        #pragma unroll
        for (int mf = 0; mf < 2; mf++)
            ldsm4(af[0][mf][0], af[0][mf][1], af[0][mf][2], af[0][mf][3],
                  stA + a_off[mf]);
        #pragma unroll
        for (int nf2 = 0; nf2 < 4; nf2++) {
            uint32_t r0, r1, r2, r3;
            ldsm4(r0, r1, r2, r3, stW + b_off[nf2]);
            bf[0][nf2 * 2][0] = r0; bf[0][nf2 * 2][1] = r1;
            bf[0][nf2 * 2 + 1][0] = r2; bf[0][nf2 * 2 + 1][1] = r3;
        }

        #pragma unroll
        for (int ks = 0; ks < 4; ks++) {
            const int cur = ks & 1;
            const int nxt = cur ^ 1;
            if (ks < 3) {
                const uint32_t kx = (ks + 1) * 32;
                #pragma unroll
                for (int mf = 0; mf < 2; mf++)
                    ldsm4(af[nxt][mf][0], af[nxt][mf][1], af[nxt][mf][2], af[nxt][mf][3],
                          stA + (a_off[mf] ^ kx));
                #pragma unroll
                for (int nf2 = 0; nf2 < 4; nf2++) {
                    uint32_t r0, r1, r2, r3;
                    ldsm4(r0, r1, r2, r3, stW + (b_off[nf2] ^ kx));
                    bf[nxt][nf2 * 2][0] = r0; bf[nxt][nf2 * 2][1] = r1;
                    bf[nxt][nf2 * 2 + 1][0] = r2; bf[nxt][nf2 * 2 + 1][1] = r3;
                }
            }
            #pragma unroll
            for (int mf = 0; mf < 2; mf++)
                #pragma unroll
                for (int nf = 0; nf < 8; nf++)
                    mma16816h(acc[mf][nf][0], acc[mf][nf][1],
                              af[cur][mf][0], af[cur][mf][1], af[cur][mf][2], af[cur][mf][3],
                              bf[cur][nf][0], bf[cur][nf][1]);
        }
    }

    #pragma unroll
    for (int mf = 0; mf < 2; mf++) {
        int r0 = m0 + warp_m * 32 + mf * 16 + (lane >> 2);
        #pragma unroll
        for (int nf = 0; nf < 8; nf++) {
            int n = n0 + warp_n * 64 + nf * 8 + (lane & 3) * 2;
            __half2 bias2 = __floats2half2_rn(bias[n], bias[n + 1]);
            __half2 v0 = __hadd2(*(__half2*)&acc[mf][nf][0], bias2);
            __half2 v1 = __hadd2(*(__half2*)&acc[mf][nf][1], bias2);
            *(__half2*)(C + (size_t)r0 * N + n)       = v0;
            *(__half2*)(C + (size_t)(r0 + 8) * N + n) = v1;
        }
    }
}

// ---------------------------------------------------------------------------
// Chunked gated recurrence over fp16 zg. 16 chunks x 128 steps, 32-step
// warm-up. Writes h as fp16.
// ---------------------------------------------------------------------------
#define SCAN_CHUNKS 16
#define SCAN_L      (T_DIM / SCAN_CHUNKS)   // 128
#define SCAN_W      32

__global__ __launch_bounds__(256)
void scan_kernel(const float* __restrict__ Avec, const float* __restrict__ Bvec)
{
    int idx = blockIdx.x * blockDim.x + threadIdx.x;
    int d = idx & 511;
    int b = (idx >> 9) & 31;
    int chunk = idx >> 14;

    float a_d = Avec[d];
    float b_d = Bvec[d];
    const __half* zg = g_zgh + (size_t)b * (2 * D_DIM) + d;
    __half* hp = g_hh + (size_t)b * D_DIM + d;
    const size_t zs = (size_t)B_DIM * 2 * D_DIM;
    const size_t hs = (size_t)B_DIM * D_DIM;

    const int t0 = chunk * SCAN_L;
    const int tw = (chunk == 0) ? 0 : t0 - SCAN_W;

    float h = 0.f;
    for (int t = tw; t < t0; t += 8) {
        float zz[8], gg[8];
        #pragma unroll
        for (int i = 0; i < 8; i++) {
            zz[i] = __half2float(zg[(size_t)(t + i) * zs]);
            gg[i] = __half2float(zg[(size_t)(t + i) * zs + D_DIM]);
        }
        #pragma unroll
        for (int i = 0; i < 8; i++) {
            float g = 1.f / (1.f + __expf(-gg[i]));
            h = fmaf(g * a_d, h, b_d * zz[i]);
        }
    }
    for (int t = t0; t < t0 + SCAN_L; t += 8) {
        float zz[8], gg[8];
        #pragma unroll
        for (int i = 0; i < 8; i++) {
            zz[i] = __half2float(zg[(size_t)(t + i) * zs]);
            gg[i] = __half2float(zg[(size_t)(t + i) * zs + D_DIM]);
        }
        #pragma unroll
        for (int i = 0; i < 8; i++) {
            float g = 1.f / (1.f + __expf(-gg[i]));
            h = fmaf(g * a_d, h, b_d * zz[i]);
            hp[(size_t)(t + i) * hs] = __float2half_rn(h);
        }
    }
}

// ---------------------------------------------------------------------------
// LayerNorm(xh + proj): both fp16, fp32 accumulate -> fp32 out
// ---------------------------------------------------------------------------
__global__ __launch_bounds__(128)
void ln_kernel(const __half* __restrict__ xh, const __half* __restrict__ proj,
               const float* __restrict__ gamma, const float* __restrict__ beta,
               float* __restrict__ out)
{
    const size_t r = blockIdx.x;
    const __half* xr = xh + r * D_DIM;
    const __half* pr = proj + r * D_DIM;
    float* orow = out + r * D_DIM;
    const int t = threadIdx.x;

    float v[4];
    {
        __half2 x0 = *(const __half2*)(xr + t * 4);
        __half2 x1 = *(const __half2*)(xr + t * 4 + 2);
        __half2 p0 = *(const __half2*)(pr + t * 4);
        __half2 p1 = *(const __half2*)(pr + t * 4 + 2);
        float2 fx0 = __half22float2(x0), fx1 = __half22float2(x1);
        float2 fp0 = __half22float2(p0), fp1 = __half22float2(p1);
        v[0] = fx0.x + fp0.x; v[1] = fx0.y + fp0.y;
        v[2] = fx1.x + fp1.x; v[3] = fx1.y + fp1.y;
    }
    float s1 = v[0] + v[1] + v[2] + v[3];
    float s2 = v[0] * v[0] + v[1] * v[1] + v[2] * v[2] + v[3] * v[3];

    #pragma unroll
    for (int off = 16; off; off >>= 1) {
        s1 += __shfl_xor_sync(0xffffffffu, s1, off);
        s2 += __shfl_xor_sync(0xffffffffu, s2, off);
    }
    __shared__ float sh1[4], sh2[4];
    int w = t >> 5;
    if ((t & 31) == 0) { sh1[w] = s1; sh2[w] = s2; }
    __syncthreads();
    s1 = sh1[0] + sh1[1] + sh1[2] + sh1[3];
    s2 = sh2[0] + sh2[1] + sh2[2] + sh2[3];

    float mu  = s1 * (1.f / D_DIM);
    float var = s2 * (1.f / D_DIM) - mu * mu;
    float rs  = rsqrtf(var + 1e-5f);

    float4 o;
    o.x = (v[0] - mu) * rs * gamma[t * 4]     + beta[t * 4];
    o.y = (v[1] - mu) * rs * gamma[t * 4 + 1] + beta[t * 4 + 1];
    o.z = (v[2] - mu) * rs * gamma[t * 4 + 2] + beta[t * 4 + 2];
    o.w = (v[3] - mu) * rs * gamma[t * 4 + 3] + beta[t * 4 + 3];
    *(float4*)(orow + t * 4) = o;
}

// ---------------------------------------------------------------------------
extern "C" void kernel_launch(void* const* d_in, const int* in_sizes, int n_in,
                              void* d_out, int out_size)
{
    const float* x     = (const float*)d_in[0];
    const float* W_in  = (const float*)d_in[1];
    const float* b_in  = (const float*)d_in[2];
    const float* W_out = (const float*)d_in[3];
    const float* b_out = (const float*)d_in[4];
    const float* Avec  = (const float*)d_in[5];
    const float* Bvec  = (const float*)d_in[6];
    const float* gamma = (const float*)d_in[7];
    const float* beta  = (const float*)d_in[8];
    float* out = (float*)d_out;

    __half *zgh, *xh, *ph, *hh, *wih, *woh;
    cudaGetSymbolAddress((void**)&zgh, g_zgh);
    cudaGetSymbolAddress((void**)&xh,  g_xh);
    cudaGetSymbolAddress((void**)&ph,  g_ph);
    cudaGetSymbolAddress((void**)&hh,  g_hh);
    cudaGetSymbolAddress((void**)&wih, g_wih);
    cudaGetSymbolAddress((void**)&woh, g_woh);

    cudaFuncSetAttribute(gemm_mma, cudaFuncAttributeMaxDynamicSharedMemorySize,
                         SMEM_GEMM);
    cudaFuncSetAttribute(gemm_mma_h16, cudaFuncAttributeMaxDynamicSharedMemorySize,
                         SMEM_GEMM);

    // Merged converts (x, W_in, W_out -> fp16)
    {
        size_t total = N4_X + N4_WI + N4_WO;
        cvt_all_kernel<<<(unsigned)((total + 255) / 256), 256>>>(
            x, W_in, W_out, xh, wih, woh);
    }

    // GEMM1: zg[M, 2D] = x * W_in^T + b_in  (fp32 acc, fp16 out)
    gemm_mma<<<dim3(2 * D_DIM / 128, M_DIM / 128), 256, SMEM_GEMM>>>(
        xh, wih, b_in, zgh, 2 * D_DIM);

    // Chunked gated scan -> h (fp16)
    scan_kernel<<<(SCAN_CHUNKS * B_DIM * D_DIM) / 256, 256>>>(Avec, Bvec);

    // GEMM2: proj[M, D] = h * W_out^T + b_out  (fp16 acc, fp16 out)
    gemm_mma_h16<<<dim3(D_DIM / 128, M_DIM / 128), 256, SMEM_GEMM>>>(
        hh, woh, b_out, ph, D_DIM);

    // LayerNorm(xh + proj) -> out (both residual inputs fp16)
    ln_kernel<<<M_DIM, 128>>>(xh, ph, gamma, beta, out);
}

// round 16
// speedup vs baseline: 1.0563x; 1.0263x over previous
#include <cuda_runtime.h>
#include <cuda_fp16.h>
#include <cstdint>
#include <math.h>

#define T_DIM 2048
#define B_DIM 32
#define D_DIM 512
#define M_DIM (T_DIM * B_DIM)     // 65536
#define KGL   512

// ---------------------------------------------------------------------------
// Device-global scratch
// ---------------------------------------------------------------------------
__device__ __half g_zgh[(size_t)M_DIM * 2 * D_DIM];   // [M, 2D] fp16
__device__ __half g_xh [(size_t)M_DIM * D_DIM];       // x fp16
__device__ __half g_ph [(size_t)M_DIM * D_DIM];       // proj fp16
__device__ __half g_hh [(size_t)M_DIM * D_DIM];       // h fp16
__device__ __half g_wih[2 * D_DIM * D_DIM];           // W_in  fp16
__device__ __half g_woh[D_DIM * D_DIM];               // W_out fp16

// ---------------------------------------------------------------------------
// Helpers
// ---------------------------------------------------------------------------
__device__ __forceinline__ uint32_t s2u(const void* p) {
    return (uint32_t)__cvta_generic_to_shared(p);
}
__device__ __forceinline__ uint32_t swz(uint32_t off) {
    return off ^ ((off >> 3) & 0x70);
}
__device__ __forceinline__ void cpa16(uint32_t saddr, const void* g) {
    asm volatile("cp.async.cg.shared.global [%0], [%1], 16;" :: "r"(saddr), "l"(g));
}
#define CP_COMMIT() asm volatile("cp.async.commit_group;" ::: "memory")
#define CP_WAIT1()  asm volatile("cp.async.wait_group 1;" ::: "memory")
#define CP_WAIT0()  asm volatile("cp.async.wait_group 0;" ::: "memory")

__device__ __forceinline__ void ldsm4(uint32_t& r0, uint32_t& r1,
                                      uint32_t& r2, uint32_t& r3, uint32_t a) {
    asm volatile("ldmatrix.sync.aligned.m8n8.x4.shared.b16 {%0,%1,%2,%3}, [%4];"
                 : "=r"(r0), "=r"(r1), "=r"(r2), "=r"(r3) : "r"(a));
}
__device__ __forceinline__ void mma16816h(uint32_t& c0, uint32_t& c1,
                                          uint32_t a0, uint32_t a1, uint32_t a2, uint32_t a3,
                                          uint32_t b0, uint32_t b1) {
    asm volatile(
        "mma.sync.aligned.m16n8k16.row.col.f16.f16.f16.f16 "
        "{%0,%1}, {%2,%3,%4,%5}, {%6,%7}, {%0,%1};"
        : "+r"(c0), "+r"(c1)
        : "r"(a0), "r"(a1), "r"(a2), "r"(a3), "r"(b0), "r"(b1));
}

// ---------------------------------------------------------------------------
// Merged fp32 -> fp16 convert for x, W_in, W_out (one launch)
// ---------------------------------------------------------------------------
#define N4_X  ((size_t)M_DIM * D_DIM / 4)
#define N4_WI ((size_t)2 * D_DIM * D_DIM / 4)
#define N4_WO ((size_t)D_DIM * D_DIM / 4)

__global__ void cvt_all_kernel(const float* __restrict__ x,
                               const float* __restrict__ wi,
                               const float* __restrict__ wo,
                               __half* __restrict__ xh,
                               __half* __restrict__ wih,
                               __half* __restrict__ woh)
{
    size_t i = blockIdx.x * (size_t)blockDim.x + threadIdx.x;
    const float* in; __half* out; size_t j;
    if (i < N4_X)                      { in = x;  out = xh;  j = i; }
    else if (i < N4_X + N4_WI)         { in = wi; out = wih; j = i - N4_X; }
    else if (i < N4_X + N4_WI + N4_WO) { in = wo; out = woh; j = i - N4_X - N4_WI; }
    else return;
    float4 v = ((const float4*)in)[j];
    ((__half2*)out)[2 * j]     = __floats2half2_rn(v.x, v.y);
    ((__half2*)out)[2 * j + 1] = __floats2half2_rn(v.z, v.w);
}

// ---------------------------------------------------------------------------
// fp16-acc GEMM, 2-stage double buffer, minimal registers for occ=3.
// 128x128 block tile, 8 warps (4x2), warp tile 32x64, BK=64.
// ---------------------------------------------------------------------------
#define BK        64
#define STAGES    2
#define TILE_B    (128 * 128)
#define STAGE_B   (2 * TILE_B)
#define SMEM_GEMM (STAGES * STAGE_B)       // 65536

__device__ __forceinline__ void load_stage(
    uint32_t sbase, int s, int chunk, int m0, int n0, int tid,
    const __half* __restrict__ A, const __half* __restrict__ W)
{
    const int k0 = chunk * BK;
    uint32_t stA = sbase + s * STAGE_B;
    uint32_t stW = stA + TILE_B;

    #pragma unroll
    for (int i = 0; i < 4; i++) {
        int g   = tid + i * 256;
        int row = g >> 3;
        int c16 = g & 7;
        uint32_t so = swz(row * 128 + c16 * 16);
        cpa16(stA + so, A + (size_t)(m0 + row) * KGL + k0 + c16 * 8);
        cpa16(stW + so, W + (size_t)(n0 + row) * KGL + k0 + c16 * 8);
    }
    CP_COMMIT();
}

__global__ __launch_bounds__(256, 3)
void gemm_h16(const __half* __restrict__ A, const __half* __restrict__ W,
              const float* __restrict__ bias, __half* __restrict__ C, int N)
{
    extern __shared__ char smem[];
    const uint32_t sb = s2u(smem);
    const int tid    = threadIdx.x;
    const int lane   = tid & 31;
    const int wid    = tid >> 5;
    const int warp_m = wid & 3;
    const int warp_n = wid >> 2;
    const int m0 = blockIdx.y * 128;
    const int n0 = blockIdx.x * 128;
    const int NCHUNK = KGL / BK;           // 8

    uint32_t a_off[2], b_off[4];
    #pragma unroll
    for (int mf = 0; mf < 2; mf++) {
        uint32_t row = warp_m * 32 + mf * 16 + (lane & 15);
        a_off[mf] = swz(row * 128 + (lane >> 4) * 16);
    }
    #pragma unroll
    for (int nf2 = 0; nf2 < 4; nf2++) {
        uint32_t row = warp_n * 64 + nf2 * 16 + (lane & 7) + ((lane >> 4) << 3);
        b_off[nf2] = swz(row * 128 + ((lane >> 3) & 1) * 16);
    }

    uint32_t acc[2][8][2];
    #pragma unroll
    for (int i = 0; i < 2; i++)
        #pragma unroll
        for (int j = 0; j < 8; j++) { acc[i][j][0] = 0u; acc[i][j][1] = 0u; }

    load_stage(sb, 0, 0, m0, n0, tid, A, W);
    load_stage(sb, 1, 1, m0, n0, tid, A, W);

    #pragma unroll 1
    for (int c = 0; c < NCHUNK; c++) {
        const int s = c & 1;
        if (c + 1 < NCHUNK) { CP_WAIT1(); } else { CP_WAIT0(); }
        __syncthreads();

        const uint32_t stA = sb + s * STAGE_B;
        const uint32_t stW = stA + TILE_B;

        #pragma unroll
        for (int ks = 0; ks < 4; ks++) {
            const uint32_t kx = ks * 32;
            uint32_t af[2][4];
            #pragma unroll
            for (int mf = 0; mf < 2; mf++)
                ldsm4(af[mf][0], af[mf][1], af[mf][2], af[mf][3],
                      stA + (a_off[mf] ^ kx));
            uint32_t bf[8][2];
            #pragma unroll
            for (int nf2 = 0; nf2 < 4; nf2++) {
                uint32_t r0, r1, r2, r3;
                ldsm4(r0, r1, r2, r3, stW + (b_off[nf2] ^ kx));
                bf[nf2 * 2][0] = r0; bf[nf2 * 2][1] = r1;
                bf[nf2 * 2 + 1][0] = r2; bf[nf2 * 2 + 1][1] = r3;
            }
            #pragma unroll
            for (int mf = 0; mf < 2; mf++)
                #pragma unroll
                for (int nf = 0; nf < 8; nf++)
                    mma16816h(acc[mf][nf][0], acc[mf][nf][1],
                              af[mf][0], af[mf][1], af[mf][2], af[mf][3],
                              bf[nf][0], bf[nf][1]);
        }

        __syncthreads();                   // buffer s fully consumed
        if (c + 2 < NCHUNK)
            load_stage(sb, s, c + 2, m0, n0, tid, A, W);
    }

    // Epilogue: add bias (fp16), store fp16
    #pragma unroll
    for (int mf = 0; mf < 2; mf++) {
        int r0 = m0 + warp_m * 32 + mf * 16 + (lane >> 2);
        #pragma unroll
        for (int nf = 0; nf < 8; nf++) {
            int n = n0 + warp_n * 64 + nf * 8 + (lane & 3) * 2;
            __half2 bias2 = __floats2half2_rn(bias[n], bias[n + 1]);
            __half2 v0 = __hadd2(*(__half2*)&acc[mf][nf][0], bias2);
            __half2 v1 = __hadd2(*(__half2*)&acc[mf][nf][1], bias2);
            *(__half2*)(C + (size_t)r0 * N + n)       = v0;
            *(__half2*)(C + (size_t)(r0 + 8) * N + n) = v1;
        }
    }
}

// ---------------------------------------------------------------------------
// Chunked gated recurrence over fp16 zg. 16 chunks x 128 steps, 32-step
// warm-up. Writes h as fp16.
// ---------------------------------------------------------------------------
#define SCAN_CHUNKS 16
#define SCAN_L      (T_DIM / SCAN_CHUNKS)   // 128
#define SCAN_W      32

__global__ __launch_bounds__(256)
void scan_kernel(const float* __restrict__ Avec, const float* __restrict__ Bvec)
{
    int idx = blockIdx.x * blockDim.x + threadIdx.x;
    int d = idx & 511;
    int b = (idx >> 9) & 31;
    int chunk = idx >> 14;

    float a_d = Avec[d];
    float b_d = Bvec[d];
    const __half* zg = g_zgh + (size_t)b * (2 * D_DIM) + d;
    __half* hp = g_hh + (size_t)b * D_DIM + d;
    const size_t zs = (size_t)B_DIM * 2 * D_DIM;
    const size_t hs = (size_t)B_DIM * D_DIM;

    const int t0 = chunk * SCAN_L;
    const int tw = (chunk == 0) ? 0 : t0 - SCAN_W;

    float h = 0.f;
    for (int t = tw; t < t0; t += 8) {
        float zz[8], gg[8];
        #pragma unroll
        for (int i = 0; i < 8; i++) {
            zz[i] = __half2float(zg[(size_t)(t + i) * zs]);
            gg[i] = __half2float(zg[(size_t)(t + i) * zs + D_DIM]);
        }
        #pragma unroll
        for (int i = 0; i < 8; i++) {
            float g = 1.f / (1.f + __expf(-gg[i]));
            h = fmaf(g * a_d, h, b_d * zz[i]);
        }
    }
    for (int t = t0; t < t0 + SCAN_L; t += 8) {
        float zz[8], gg[8];
        #pragma unroll
        for (int i = 0; i < 8; i++) {
            zz[i] = __half2float(zg[(size_t)(t + i) * zs]);
            gg[i] = __half2float(zg[(size_t)(t + i) * zs + D_DIM]);
        }
        #pragma unroll
        for (int i = 0; i < 8; i++) {
            float g = 1.f / (1.f + __expf(-gg[i]));
            h = fmaf(g * a_d, h, b_d * zz[i]);
            hp[(size_t)(t + i) * hs] = __float2half_rn(h);
        }
    }
}

// ---------------------------------------------------------------------------
// LayerNorm(x + proj): x fp32, proj fp16 -> out fp32 (R13 proven)
// ---------------------------------------------------------------------------
__global__ __launch_bounds__(128)
void ln_kernel(const float* __restrict__ x, const __half* __restrict__ proj,
               const float* __restrict__ gamma, const float* __restrict__ beta,
               float* __restrict__ out)
{
    const size_t r = blockIdx.x;
    const float* xr = x + r * D_DIM;
    const __half* pr = proj + r * D_DIM;
    float* orow = out + r * D_DIM;
    const int t = threadIdx.x;

    float v[4];
    {
        float4 xv = *(const float4*)(xr + t * 4);
        __half2 p0 = *(const __half2*)(pr + t * 4);
        __half2 p1 = *(const __half2*)(pr + t * 4 + 2);
        float2 f0 = __half22float2(p0);
        float2 f1 = __half22float2(p1);
        v[0] = xv.x + f0.x; v[1] = xv.y + f0.y;
        v[2] = xv.z + f1.x; v[3] = xv.w + f1.y;
    }
    float s1 = v[0] + v[1] + v[2] + v[3];
    float s2 = v[0] * v[0] + v[1] * v[1] + v[2] * v[2] + v[3] * v[3];

    #pragma unroll
    for (int off = 16; off; off >>= 1) {
        s1 += __shfl_xor_sync(0xffffffffu, s1, off);
        s2 += __shfl_xor_sync(0xffffffffu, s2, off);
    }
    __shared__ float sh1[4], sh2[4];
    int w = t >> 5;
    if ((t & 31) == 0) { sh1[w] = s1; sh2[w] = s2; }
    __syncthreads();
    s1 = sh1[0] + sh1[1] + sh1[2] + sh1[3];
    s2 = sh2[0] + sh2[1] + sh2[2] + sh2[3];

    float mu  = s1 * (1.f / D_DIM);
    float var = s2 * (1.f / D_DIM) - mu * mu;
    float rs  = rsqrtf(var + 1e-5f);

    float4 o;
    o.x = (v[0] - mu) * rs * gamma[t * 4]     + beta[t * 4];
    o.y = (v[1] - mu) * rs * gamma[t * 4 + 1] + beta[t * 4 + 1];
    o.z = (v[2] - mu) * rs * gamma[t * 4 + 2] + beta[t * 4 + 2];
    o.w = (v[3] - mu) * rs * gamma[t * 4 + 3] + beta[t * 4 + 3];
    *(float4*)(orow + t * 4) = o;
}

// ---------------------------------------------------------------------------
extern "C" void kernel_launch(void* const* d_in, const int* in_sizes, int n_in,
                              void* d_out, int out_size)
{
    const float* x     = (const float*)d_in[0];
    const float* W_in  = (const float*)d_in[1];
    const float* b_in  = (const float*)d_in[2];
    const float* W_out = (const float*)d_in[3];
    const float* b_out = (const float*)d_in[4];
    const float* Avec  = (const float*)d_in[5];
    const float* Bvec  = (const float*)d_in[6];
    const float* gamma = (const float*)d_in[7];
    const float* beta  = (const float*)d_in[8];
    float* out = (float*)d_out;

    __half *zgh, *xh, *ph, *hh, *wih, *woh;
    cudaGetSymbolAddress((void**)&zgh, g_zgh);
    cudaGetSymbolAddress((void**)&xh,  g_xh);
    cudaGetSymbolAddress((void**)&ph,  g_ph);
    cudaGetSymbolAddress((void**)&hh,  g_hh);
    cudaGetSymbolAddress((void**)&wih, g_wih);
    cudaGetSymbolAddress((void**)&woh, g_woh);

    cudaFuncSetAttribute(gemm_h16, cudaFuncAttributeMaxDynamicSharedMemorySize,
                         SMEM_GEMM);

    // Merged converts (x, W_in, W_out -> fp16)
    {
        size_t total = N4_X + N4_WI + N4_WO;
        cvt_all_kernel<<<(unsigned)((total + 255) / 256), 256>>>(
            x, W_in, W_out, xh, wih, woh);
    }

    // GEMM1: zg[M, 2D] = x * W_in^T + b_in  (fp16 acc, fp16 out)
    gemm_h16<<<dim3(2 * D_DIM / 128, M_DIM / 128), 256, SMEM_GEMM>>>(
        xh, wih, b_in, zgh, 2 * D_DIM);

    // Chunked gated scan -> h (fp16)
    scan_kernel<<<(SCAN_CHUNKS * B_DIM * D_DIM) / 256, 256>>>(Avec, Bvec);

    // GEMM2: proj[M, D] = h * W_out^T + b_out  (fp16 acc, fp16 out)
    gemm_h16<<<dim3(D_DIM / 128, M_DIM / 128), 256, SMEM_GEMM>>>(
        hh, woh, b_out, ph, D_DIM);

    // LayerNorm(x + proj) -> out
    ln_kernel<<<M_DIM, 128>>>(x, ph, gamma, beta, out);
}